// round 7
// baseline (speedup 1.0000x reference)
#include <cuda_runtime.h>

#define NTOK 4096
#define NP1  4097
#define ROWS 512
#define THREADS 512

__device__ unsigned g_packed[ROWS * NTOK];   // compacted (pos<<16|content) per row
__device__ int      g_cnt[ROWS * 2];         // c0, c1 per row

// ---------------- kernel 1: scan + scatter to scratch ----------------
__global__ __launch_bounds__(THREADS)
void scan_kernel(const int* __restrict__ indices,
                 const int* __restrict__ grains)
{
    __shared__ unsigned wsum[16];
    const int b    = blockIdx.x;
    const int tid  = threadIdx.x;
    const int lane = tid & 31;
    const int warp = tid >> 5;

    const int4* iv = (const int4*)(indices + (long long)b * NTOK);
    const int4* gv = (const int4*)(grains  + (long long)b * NTOK);
    int4 ia = iv[tid * 2], ib = iv[tid * 2 + 1];
    int4 ga = gv[tid * 2], gb = gv[tid * 2 + 1];
    int v[8] = {ia.x, ia.y, ia.z, ia.w, ib.x, ib.y, ib.z, ib.w};
    int g[8] = {ga.x, ga.y, ga.z, ga.w, gb.x, gb.y, gb.z, gb.w};

    unsigned packed = 0;
#pragma unroll
    for (int i = 0; i < 8; i++)
        packed += (g[i] == 0) ? 1u : ((g[i] == 1) ? 0x10000u : 0u);

    unsigned p = packed;
#pragma unroll
    for (int d = 1; d < 32; d <<= 1) {
        unsigned t = __shfl_up_sync(0xffffffffu, p, d);
        if (lane >= d) p += t;
    }
    if (lane == 31) wsum[warp] = p;
    __syncthreads();
    if (warp == 0 && lane < 16) {
        unsigned x = wsum[lane];
#pragma unroll
        for (int d = 1; d < 16; d <<= 1) {
            unsigned t = __shfl_up_sync(0x0000ffffu, x, d);
            if (lane >= d) x += t;
        }
        wsum[lane] = x;
    }
    __syncthreads();
    const unsigned excl  = p - packed + (warp ? wsum[warp - 1] : 0u);
    const unsigned total = wsum[15];

    const int e0 = (int)(excl & 0xFFFFu), e1 = (int)(excl >> 16);
    const int c0 = (int)(total & 0xFFFFu), c1 = (int)(total >> 16);

    unsigned* __restrict__ row = g_packed + (long long)b * NTOK;
    int q0 = e0;
    int q1 = c0 + e1;
    int q2 = c0 + c1 + (tid * 8 - e0 - e1);
    const int t0 = tid * 8;
#pragma unroll
    for (int i = 0; i < 8; i++) {
        const int gi = g[i];
        const unsigned w = (unsigned)v[i] | ((unsigned)(t0 + i) << 16);
        if (gi == 0)      row[q0++] = w;
        else if (gi == 1) row[q1++] = w;
        else              row[q2++] = w;
    }
    if (tid == 0) { g_cnt[b * 2] = c0; g_cnt[b * 2 + 1] = c1; }
}

// ---------------- kernel 2: parallel fill ----------------
__device__ __forceinline__ float lo_f(unsigned w) { return (float)(unsigned short)(w & 0xFFFFu); }
__device__ __forceinline__ float hi_f(unsigned w) { return (float)(unsigned short)(w >> 16); }

__device__ __forceinline__ float compL(const unsigned* __restrict__ buf, int j,
                                       int cnt, float eos, float pad)
{ return j < cnt ? lo_f(__ldg(buf + j)) : (j == cnt ? eos : pad); }

__device__ __forceinline__ float compH(const unsigned* __restrict__ buf, int j,
                                       int cnt, float eos, float pad)
{ return j < cnt ? hi_f(__ldg(buf + j)) : (j == cnt ? eos : pad); }

__global__ __launch_bounds__(THREADS)
void fill_kernel(float* __restrict__ out, long long M)
{
    const int b   = blockIdx.x;
    const int s   = blockIdx.y;       // 0..2 = stream pair, 3 = constants
    const int tid = threadIdx.x;
    const long long rb = (long long)b * NP1;

    // shared head offset h (M % 4 == 0 so all 9 rows of a given b align equally)
    float* __restrict__ base0 = out + rb;
    const int h  = (int)((0u - ((unsigned)(size_t)base0 >> 2)) & 3u);
    const int nv = (NP1 - h) >> 2;
    const int tb = h + nv * 4;        // tail base

    if (s == 3) {                     // three constant segment rows
        float* __restrict__ d0 = out + 6 * M + rb;
        float* __restrict__ d1 = out + 7 * M + rb;
        float* __restrict__ d2 = out + 8 * M + rb;
        if (tid < h) { d0[tid] = 0.f; d1[tid] = 1.f; d2[tid] = 2.f; }
        float4* __restrict__ a4 = (float4*)(d0 + h);
        float4* __restrict__ b4 = (float4*)(d1 + h);
        float4* __restrict__ c4 = (float4*)(d2 + h);
        const float4 z = make_float4(0.f,0.f,0.f,0.f);
        const float4 o = make_float4(1.f,1.f,1.f,1.f);
        const float4 t = make_float4(2.f,2.f,2.f,2.f);
#pragma unroll 2
        for (int i = tid; i < nv; i += THREADS) { a4[i] = z; b4[i] = o; c4[i] = t; }
        for (int j = tb + tid; j < NP1; j += THREADS) { d0[j]=0.f; d1[j]=1.f; d2[j]=2.f; }
        return;
    }

    const int c0 = g_cnt[b * 2], c1 = g_cnt[b * 2 + 1];
    int rbase, cnt;
    float eosP, padP;
    if (s == 0)      { rbase = 0;       cnt = c0;               eosP = 129.f;  padP = 128.f;  }
    else if (s == 1) { rbase = c0;      cnt = c1;               eosP = 257.f;  padP = 256.f;  }
    else             { rbase = c0 + c1; cnt = NTOK - c0 - c1;   eosP = 1025.f; padP = 1024.f; }
    const float eosC = 1025.f, padC = 1024.f;

    const unsigned* __restrict__ buf = g_packed + (long long)b * NTOK + rbase;
    float* __restrict__ dstC = out + (long long)s * M + rb;
    float* __restrict__ dstP = out + (long long)(3 + s) * M + rb;

    if (tid < h) {
        dstC[tid] = compL(buf, tid, cnt, eosC, padC);
        dstP[tid] = compH(buf, tid, cnt, eosP, padP);
    }
    float4* __restrict__ c4 = (float4*)(dstC + h);
    float4* __restrict__ p4 = (float4*)(dstP + h);

    int i_c = (cnt >= h) ? ((cnt - h) >> 2) : 0;  if (i_c > nv) i_c = nv;
    int i_p = (cnt >= h) ? (i_c + 1) : 0;         if (i_p > nv) i_p = nv;

#pragma unroll 2
    for (int i = tid; i < i_c; i += THREADS) {
        const int j = h + i * 4;
        const unsigned w0 = __ldg(buf + j),     w1 = __ldg(buf + j + 1);
        const unsigned w2 = __ldg(buf + j + 2), w3 = __ldg(buf + j + 3);
        c4[i] = make_float4(lo_f(w0), lo_f(w1), lo_f(w2), lo_f(w3));
        p4[i] = make_float4(hi_f(w0), hi_f(w1), hi_f(w2), hi_f(w3));
    }
    if (tid == 0) {
        for (int i = i_c; i < i_p; i++) {
            const int j = h + i * 4;
            c4[i] = make_float4(compL(buf, j,   cnt, eosC, padC),
                                compL(buf, j+1, cnt, eosC, padC),
                                compL(buf, j+2, cnt, eosC, padC),
                                compL(buf, j+3, cnt, eosC, padC));
            p4[i] = make_float4(compH(buf, j,   cnt, eosP, padP),
                                compH(buf, j+1, cnt, eosP, padP),
                                compH(buf, j+2, cnt, eosP, padP),
                                compH(buf, j+3, cnt, eosP, padP));
        }
    }
    const float4 pc = make_float4(padC, padC, padC, padC);
    const float4 pp = make_float4(padP, padP, padP, padP);
#pragma unroll 2
    for (int i = i_p + tid; i < nv; i += THREADS) { c4[i] = pc; p4[i] = pp; }
    for (int j = tb + tid; j < NP1; j += THREADS) {
        dstC[j] = compL(buf, j, cnt, eosC, padC);
        dstP[j] = compH(buf, j, cnt, eosP, padP);
    }
}

extern "C" void kernel_launch(void* const* d_in, const int* in_sizes, int n_in,
                              void* d_out, int out_size)
{
    const int* indices = (const int*)d_in[0];
    const int* grains  = (const int*)d_in[1];
    const int rows = in_sizes[0] / NTOK;            // 512
    const long long M = (long long)out_size / 9;
    scan_kernel<<<rows, THREADS>>>(indices, grains);
    dim3 grid2(rows, 4);
    fill_kernel<<<grid2, THREADS>>>((float*)d_out, M);
}

// round 8
// speedup vs baseline: 1.4105x; 1.4105x over previous
#include <cuda_runtime.h>

#define NTOK 4096
#define NP1  4097
#define THREADS 512

__device__ __forceinline__ float comp(const float* __restrict__ buf, int off, int j,
                                      int cnt, float eos, float pad)
{ return j < cnt ? buf[j + off] : (j == cnt ? eos : pad); }

// Write one row of NP1 floats: buf[off..off+cnt) then EOS then PAD.
// (base+off+h) is 0 mod 4 -> aligned LDS.128 in the hot loop, no converts.
__device__ __forceinline__ void write_row(float* __restrict__ dst,
                                          const float* __restrict__ buf, int off,
                                          int cnt, float eos, float pad,
                                          int tid, int h)
{
    if (tid < h) dst[tid] = comp(buf, off, tid, cnt, eos, pad);
    const int nv = (NP1 - h) >> 2;
    const float4* __restrict__ b4 = (const float4*)(buf + off + h);
    float4* __restrict__ d4 = (float4*)(dst + h);

    int i_c = (cnt >= h) ? ((cnt - h) >> 2) : 0;  if (i_c > nv) i_c = nv;
    int i_p = (cnt >= h) ? (i_c + 1) : 0;         if (i_p > nv) i_p = nv;

#pragma unroll 2
    for (int i = tid; i < i_c; i += THREADS) d4[i] = b4[i];      // content chunks
    if (tid == 0) {                                              // boundary chunk
        for (int i = i_c; i < i_p; i++) {
            const int s = h + i * 4;
            d4[i] = make_float4(comp(buf, off, s,     cnt, eos, pad),
                                comp(buf, off, s + 1, cnt, eos, pad),
                                comp(buf, off, s + 2, cnt, eos, pad),
                                comp(buf, off, s + 3, cnt, eos, pad));
        }
    }
    const float4 pp = make_float4(pad, pad, pad, pad);
#pragma unroll 2
    for (int i = i_p + tid; i < nv; i += THREADS) d4[i] = pp;    // pad chunks
    const int base = h + nv * 4;
    for (int j = base + tid; j < NP1; j += THREADS)              // tail (<=1 elem)
        dst[j] = comp(buf, off, j, cnt, eos, pad);
}

__device__ __forceinline__ void write_const_row(float* __restrict__ dst, float val,
                                                int tid, int h)
{
    if (tid < h) dst[tid] = val;
    const int nv = (NP1 - h) >> 2;
    float4* __restrict__ d4 = (float4*)(dst + h);
    const float4 w = make_float4(val, val, val, val);
#pragma unroll 2
    for (int i = tid; i < nv; i += THREADS) d4[i] = w;
    const int base = h + nv * 4;
    for (int j = base + tid; j < NP1; j += THREADS) dst[j] = val;
}

__global__ __launch_bounds__(THREADS)
void permute_kernel(const int* __restrict__ indices,
                    const int* __restrict__ grains,
                    float* __restrict__ out,
                    long long M)
{
    __shared__ float sb[4108];        // 3 runtime-packed stream regions (16.4 KB)
    __shared__ unsigned wsum[16];

    const int b    = blockIdx.x;
    const int role = blockIdx.y;      // 0 = content rows, 1 = position rows
    const int tid  = threadIdx.x;
    const int lane = tid & 31;
    const int warp = tid >> 5;

    // ---- issue input loads first ----
    const int4* gv = (const int4*)(grains + (long long)b * NTOK);
    int4 ga = gv[tid * 2], gb = gv[tid * 2 + 1];
    int v[8] = {0,0,0,0,0,0,0,0};
    if (role == 0) {
        const int4* iv = (const int4*)(indices + (long long)b * NTOK);
        int4 ia = iv[tid * 2], ib = iv[tid * 2 + 1];
        v[0]=ia.x; v[1]=ia.y; v[2]=ia.z; v[3]=ia.w;
        v[4]=ib.x; v[5]=ib.y; v[6]=ib.z; v[7]=ib.w;
    }
    int g[8] = {ga.x, ga.y, ga.z, ga.w, gb.x, gb.y, gb.z, gb.w};

    const long long rb = (long long)b * NP1;
    const int h = (int)((0u - ((unsigned)(size_t)(out + rb) >> 2)) & 3u);

    // ---- constant rows first: pure stores, hide load/scan latency ----
    if (role == 0) {
        write_const_row(out + 6 * M + rb, 0.0f, tid, h);
        float* __restrict__ r7 = out + 7 * M + rb;
        for (int j = tid; j < 2048; j += THREADS) r7[j] = 1.0f;
    } else {
        write_const_row(out + 8 * M + rb, 2.0f, tid, h);
        float* __restrict__ r7 = out + 7 * M + rb;
        for (int j = 2048 + tid; j < NP1; j += THREADS) r7[j] = 1.0f;
    }

    // ---- packed dual-field block scan (c0 low 16, c1 high 16) ----
    unsigned packed = 0;
#pragma unroll
    for (int i = 0; i < 8; i++)
        packed += (g[i] == 0) ? 1u : ((g[i] == 1) ? 0x10000u : 0u);
    unsigned p = packed;
#pragma unroll
    for (int d = 1; d < 32; d <<= 1) {
        unsigned t = __shfl_up_sync(0xffffffffu, p, d);
        if (lane >= d) p += t;
    }
    if (lane == 31) wsum[warp] = p;
    __syncthreads();
    if (warp == 0 && lane < 16) {
        unsigned x = wsum[lane];
#pragma unroll
        for (int d = 1; d < 16; d <<= 1) {
            unsigned t = __shfl_up_sync(0x0000ffffu, x, d);
            if (lane >= d) x += t;
        }
        wsum[lane] = x;
    }
    __syncthreads();
    const unsigned excl  = p - packed + (warp ? wsum[warp - 1] : 0u);
    const unsigned total = wsum[15];

    const int e0 = (int)(excl & 0xFFFFu), e1 = (int)(excl >> 16);
    const int c0 = (int)(total & 0xFFFFu), c1 = (int)(total >> 16);
    const int c2 = NTOK - c0 - c1;

    // ---- stream region bases (0 mod 4 so writer chunks stay 16B aligned) ----
    const int off   = (4 - h) & 3;
    const int base1 = (c0 + 3) & ~3;
    const int base2 = base1 + ((c1 + 3) & ~3);

    // ---- stable scatter (floats, converted once) ----
    int q0 = off + e0;
    int q1 = base1 + off + e1;
    int q2 = base2 + off + (tid * 8 - e0 - e1);
    const int t0 = tid * 8;
#pragma unroll
    for (int i = 0; i < 8; i++) {
        const int gi = g[i];
        const float w = (role == 0) ? (float)v[i] : (float)(t0 + i);
        if (gi == 0)      sb[q0++] = w;
        else if (gi == 1) sb[q1++] = w;
        else              sb[q2++] = w;
    }
    __syncthreads();

    // ---- write this role's 3 rows ----
    if (role == 0) {
        write_row(out + 0 * M + rb, sb,         off, c0, 1025.f, 1024.f, tid, h);
        write_row(out + 1 * M + rb, sb + base1, off, c1, 1025.f, 1024.f, tid, h);
        write_row(out + 2 * M + rb, sb + base2, off, c2, 1025.f, 1024.f, tid, h);
    } else {
        write_row(out + 3 * M + rb, sb,         off, c0,  129.f,  128.f, tid, h);
        write_row(out + 4 * M + rb, sb + base1, off, c1,  257.f,  256.f, tid, h);
        write_row(out + 5 * M + rb, sb + base2, off, c2, 1025.f, 1024.f, tid, h);
    }
}

extern "C" void kernel_launch(void* const* d_in, const int* in_sizes, int n_in,
                              void* d_out, int out_size)
{
    const int* indices = (const int*)d_in[0];
    const int* grains  = (const int*)d_in[1];
    const int rows = in_sizes[0] / NTOK;            // 512
    const long long M = (long long)out_size / 9;
    dim3 grid(rows, 2);
    permute_kernel<<<grid, THREADS>>>(indices, grains, (float*)d_out, M);
}